// round 10
// baseline (speedup 1.0000x reference)
#include <cuda_runtime.h>
#include <cuda_fp16.h>
#include <cstdint>

// ===========================================================================
// y = u @ W^T,  W = C (I-A)^{-1} B + D   (model is linear & time-invariant)
//
// Stage 1 trinv_kernel : M = (I-A)^{-1} via blocked lower-tri inversion.
//                        4 diag 32x32 inverses = 128 parallel reg-chains,
//                        then 3 levels of 32^3 GEMMs with all 1024 threads.
// Stage 2 xk_kernel    : X = M B          (128 blocks, trivially parallel)
// Stage 3 wk_kernel    : W = C X + D -> fp16 hi/lo swizzled ldmatrix images
// Stage 4 gemm_kernel  : persistent HMMA fp16 2-term GEMM,
//                        y = (uh*Wh + uh*Wl) * 2^-6, warp tile 64x32.
// NOTE: tcgen05 unusable (harness PTX targets compute_103, no 'a').
// ===========================================================================

#define SDIM 128
#define N_ROWS (32 * 8192)
#define N_TILES (N_ROWS / 128)        // 2048
#define WSCALE 64.0f
#define WSCALE_INV 0.015625f

__device__ float g_M[SDIM * SDIM];     // (I-A)^{-1}
__device__ float g_X[SDIM * SDIM];     // M B
__device__ __half g_Wh[SDIM * SDIM];   // swizzled image, hi (scaled 2^6)
__device__ __half g_Wl[SDIM * SDIM];   // swizzled image, lo (scaled 2^6)

__device__ __forceinline__ uint32_t smem_u32(const void* p) {
    return (uint32_t)__cvta_generic_to_shared(p);
}
__device__ __forceinline__ int swz_elem(int r, int k) {
    return r * 128 + ((((k >> 3) ^ (r & 7)) << 3) | (k & 7));
}

#define LDSM4(r, a) \
    asm volatile("ldmatrix.sync.aligned.m8n8.x4.shared.b16 {%0,%1,%2,%3}, [%4];" \
        : "=r"((r)[0]), "=r"((r)[1]), "=r"((r)[2]), "=r"((r)[3]) : "r"(a))

#define MMA16816H(d, a, b0, b1) \
    asm volatile("mma.sync.aligned.m16n8k16.row.col.f32.f16.f16.f32 " \
        "{%0,%1,%2,%3}, {%4,%5,%6,%7}, {%8,%9}, {%0,%1,%2,%3};" \
        : "+f"((d)[0]), "+f"((d)[1]), "+f"((d)[2]), "+f"((d)[3]) \
        : "r"((a)[0]), "r"((a)[1]), "r"((a)[2]), "r"((a)[3]), "r"(b0), "r"(b1))

// ===========================================================================
// Stage 1: M = (I-A)^{-1}, blocked lower-triangular inversion, ONE block.
// ===========================================================================
__global__ __launch_bounds__(1024, 1)
void trinv_kernel(const float* __restrict__ A) {
    extern __shared__ float sm1[];
    float* sA    = sm1;            // [128][128]
    float* sM    = sm1 + 16384;    // [128][128]
    float* sG    = sM + 16384;     // [3][32*32] scratch
    float* rdiag = sG + 3 * 1024;  // [128]

    const int tid = threadIdx.x;

    for (int i = tid; i < 4096; i += 1024) {
        ((float4*)sA)[i] = ((const float4*)A)[i];
        ((float4*)sM)[i] = make_float4(0.f, 0.f, 0.f, 0.f);
    }
    __syncthreads();
    if (tid < 128) rdiag[tid] = 1.0f / (1.0f - sA[tid * 129]);
    __syncthreads();

    // --- diagonal block inverses: 128 independent column chains -----------
    if (tid < 128) {
        const int Ib = tid >> 5, c = tid & 31, r0 = Ib * 32;
        float z[32];
        #pragma unroll
        for (int j = 0; j < 32; j++) z[j] = 0.f;
        #pragma unroll
        for (int j = 0; j < 32; j++) {
            float xj = (z[j] + ((j == c) ? 1.0f : 0.0f)) * rdiag[r0 + j];
            sM[(r0 + j) * SDIM + r0 + c] = xj;
            #pragma unroll
            for (int i2 = j + 1; i2 < 32; i2++)
                z[i2] = fmaf(sA[(r0 + i2) * SDIM + r0 + j], xj, z[i2]);
        }
    }
    __syncthreads();

    // --- off-diagonal blocks, level L = I-J --------------------------------
    for (int L = 1; L <= 3; L++) {
        const int nP = 4 - L;
        // G_p = sum_{K=J}^{I-1} A[I,K] * M[K,J],  p -> (I=J+L, J=p)
        for (int e = tid; e < nP * 1024; e += 1024) {
            const int p = e >> 10, idx = e & 1023;
            const int r = idx >> 5, c = idx & 31;
            const int J = p, I = p + L;
            float acc = 0.f;
            for (int K = J; K < I; K++) {
                const float* arow = sA + (I * 32 + r) * SDIM + K * 32;
                const float* mcol = sM + (K * 32) * SDIM + J * 32 + c;
                #pragma unroll
                for (int k = 0; k < 32; k++)
                    acc = fmaf(arow[k], mcol[k * SDIM], acc);
            }
            sG[p * 1024 + idx] = acc;
        }
        __syncthreads();
        // M[I,J] = M[I,I] * G_p
        for (int e = tid; e < nP * 1024; e += 1024) {
            const int p = e >> 10, idx = e & 1023;
            const int r = idx >> 5, c = idx & 31;
            const int J = p, I = p + L;
            float acc = 0.f;
            const float* mrow = sM + (I * 32 + r) * SDIM + I * 32;
            const float* gcol = sG + p * 1024 + c;
            #pragma unroll
            for (int k = 0; k < 32; k++)
                acc = fmaf(mrow[k], gcol[k * 32], acc);
            sM[(I * 32 + r) * SDIM + J * 32 + c] = acc;
        }
        __syncthreads();
    }

    for (int i = tid; i < 4096; i += 1024)
        ((float4*)g_M)[i] = ((const float4*)sM)[i];
}

// ===========================================================================
// Stage 2: X = M B   (row s per block; M lower-tri so t <= s)
// ===========================================================================
__global__ void xk_kernel(const float* __restrict__ B) {
    const int s = blockIdx.x, d = threadIdx.x;
    float acc = 0.f;
    for (int t = 0; t <= s; t++)
        acc = fmaf(g_M[s * SDIM + t], B[t * SDIM + d], acc);
    g_X[s * SDIM + d] = acc;
}

// ===========================================================================
// Stage 3: W[o][d] = (sum_s C[o,s] X[s,d] + D[o,d]) * 2^6 -> fp16 hi/lo
// ===========================================================================
__global__ void wk_kernel(const float* __restrict__ C, const float* __restrict__ Dm) {
    const int g = blockIdx.x * blockDim.x + threadIdx.x;
    const int o = g >> 7;
    const int d = g & (SDIM - 1);
    float acc = Dm[o * SDIM + d];
    #pragma unroll 8
    for (int s = 0; s < SDIM; s++)
        acc = fmaf(C[o * SDIM + s], g_X[s * SDIM + d], acc);
    float ws = acc * WSCALE;
    __half h = __float2half_rn(ws);
    __half l = __float2half_rn(ws - __half2float(h));
    int idx = swz_elem(o, d);
    g_Wh[idx] = h;
    g_Wl[idx] = l;
}

// ===========================================================================
// Stage 4: persistent HMMA GEMM. Warp tile 64 rows x 32 cols.
// SMEM: [0,32K) Wh | [32K,64K) Wl | buf p at 64K + p*32K: Uh(32K)
// ===========================================================================
#define GSMEM_BYTES (128 * 1024)
#define UBOFF(p) (65536u + (uint32_t)(p) * 32768u)

__global__ __launch_bounds__(256, 1)
void gemm_kernel(const float* __restrict__ u, float* __restrict__ y, int grid) {
    extern __shared__ __align__(16) unsigned char sm[];
    const uint32_t sbase = smem_u32(sm);

    const int tid  = threadIdx.x;
    const int lane = tid & 31;
    const int w    = tid >> 5;
    const int rg   = w >> 2;           // 0..1 : 64-row group
    const int cq   = w & 3;            // 0..3 : 32-col quarter
    const int Rw   = rg * 64;

    // W images -> SMEM
    {
        const uint4* sh = (const uint4*)g_Wh;
        const uint4* sl = (const uint4*)g_Wl;
        uint4* dh = (uint4*)sm;
        uint4* dl = (uint4*)(sm + 32768);
        for (int i = tid; i < 2048; i += 256) { dh[i] = sh[i]; dl[i] = sl[i]; }
    }

    const int a_row  = Rw + (lane & 7) + ((lane >> 3) & 1) * 8;  // + rf*16
    const int a_kadd = ((lane >> 4) & 1) * 8;
    const int b_n    = cq * 32 + (lane & 7) + ((lane >> 4) & 1) * 8;  // + ng*16
    const int b_kadd = ((lane >> 3) & 1) * 8;
    const int r7     = lane & 7;

    float4 v[16];
    int tile = blockIdx.x;

    // ---- prologue: tile0 -> buf0; prefetch tile1 into regs ---------------
    if (tile < N_TILES) {
        const float4* src = (const float4*)u + (long)tile * 4096;
        #pragma unroll
        for (int j = 0; j < 8; j++) {
            int uid = tid + 256 * j;
            v[2 * j]     = src[uid * 2];
            v[2 * j + 1] = src[uid * 2 + 1];
        }
        #pragma unroll
        for (int j = 0; j < 8; j++) {
            int uid = tid + 256 * j;
            int row = uid >> 4, kk = uid & 15;
            float4 p0 = v[2 * j], p1 = v[2 * j + 1];
            __half2 h01 = __floats2half2_rn(p0.x, p0.y);
            __half2 h23 = __floats2half2_rn(p0.z, p0.w);
            __half2 h45 = __floats2half2_rn(p1.x, p1.y);
            __half2 h67 = __floats2half2_rn(p1.z, p1.w);
            int off = row * 256 + ((kk ^ (row & 7)) << 4);
            *(uint4*)(sm + UBOFF(0) + off) =
                make_uint4(*(uint32_t*)&h01, *(uint32_t*)&h23,
                           *(uint32_t*)&h45, *(uint32_t*)&h67);
        }
    }
    if (tile + grid < N_TILES) {
        const float4* src = (const float4*)u + (long)(tile + grid) * 4096;
        #pragma unroll
        for (int j = 0; j < 8; j++) {
            int uid = tid + 256 * j;
            v[2 * j]     = src[uid * 2];
            v[2 * j + 1] = src[uid * 2 + 1];
        }
    }
    __syncthreads();

    int p = 0;
    for (; tile < N_TILES; tile += grid) {
        const bool hasNext = (tile + grid) < N_TILES;
        const uint32_t ub  = UBOFF(p);
        const uint32_t ubn = UBOFF(p ^ 1);

        float acc[4][4][4];
        #pragma unroll
        for (int rf = 0; rf < 4; rf++)
            #pragma unroll
            for (int nt = 0; nt < 4; nt++)
                #pragma unroll
                for (int q = 0; q < 4; q++) acc[rf][nt][q] = 0.f;

        #pragma unroll
        for (int ks = 0; ks < 8; ks++) {
            const int k0 = ks * 16;
            uint32_t ah[4][4];
            {
                int mk = k0 + a_kadd;
                uint32_t ad = sbase + ub +
                    (uint32_t)(a_row * 256 + (((mk >> 3) ^ r7) << 4));
                LDSM4(ah[0], ad);
                LDSM4(ah[1], ad + 4096u);
                LDSM4(ah[2], ad + 8192u);
                LDSM4(ah[3], ad + 12288u);
            }
            #pragma unroll
            for (int ng = 0; ng < 2; ng++) {
                int n = b_n + ng * 16;
                int mk = k0 + b_kadd;
                uint32_t bd = sbase +
                    (uint32_t)(n * 256 + (((mk >> 3) ^ r7) << 4));
                uint32_t bh[4], bl[4];
                LDSM4(bh, bd);
                LDSM4(bl, bd + 32768u);
                const int nt = ng * 2;
                #pragma unroll
                for (int rf = 0; rf < 4; rf++) {
                    MMA16816H(acc[rf][nt],     ah[rf], bh[0], bh[1]);
                    MMA16816H(acc[rf][nt + 1], ah[rf], bh[2], bh[3]);
                    MMA16816H(acc[rf][nt],     ah[rf], bl[0], bl[1]);
                    MMA16816H(acc[rf][nt + 1], ah[rf], bl[2], bl[3]);
                }
            }
            // interleave next-tile convert/STS chunk
            if (hasNext) {
                int uid = tid + 256 * ks;
                int row = uid >> 4, kk = uid & 15;
                float4 p0 = v[2 * ks], p1 = v[2 * ks + 1];
                __half2 h01 = __floats2half2_rn(p0.x, p0.y);
                __half2 h23 = __floats2half2_rn(p0.z, p0.w);
                __half2 h45 = __floats2half2_rn(p1.x, p1.y);
                __half2 h67 = __floats2half2_rn(p1.z, p1.w);
                int off = row * 256 + ((kk ^ (row & 7)) << 4);
                *(uint4*)(sm + ubn + off) =
                    make_uint4(*(uint32_t*)&h01, *(uint32_t*)&h23,
                               *(uint32_t*)&h45, *(uint32_t*)&h67);
            }
        }

        // epilogue: fragments -> y, scaled by 2^-6
        {
            const int q = lane >> 2, s2 = (lane & 3) * 2;
            #pragma unroll
            for (int rf = 0; rf < 4; rf++) {
                long grow = (long)tile * 128 + Rw + rf * 16 + q;
                float* yp0 = y + grow * SDIM + cq * 32 + s2;
                #pragma unroll
                for (int nt = 0; nt < 4; nt++) {
                    *(float2*)(yp0 + nt * 8) =
                        make_float2(acc[rf][nt][0] * WSCALE_INV,
                                    acc[rf][nt][1] * WSCALE_INV);
                    *(float2*)(yp0 + 8 * SDIM + nt * 8) =
                        make_float2(acc[rf][nt][2] * WSCALE_INV,
                                    acc[rf][nt][3] * WSCALE_INV);
                }
            }
        }

        // prefetch tile t+2 into regs
        if (tile + 2 * grid < N_TILES) {
            const float4* src = (const float4*)u + (long)(tile + 2 * grid) * 4096;
            #pragma unroll
            for (int j = 0; j < 8; j++) {
                int uid = tid + 256 * j;
                v[2 * j]     = src[uid * 2];
                v[2 * j + 1] = src[uid * 2 + 1];
            }
        }
        __syncthreads();
        p ^= 1;
    }
}

// ===========================================================================
extern "C" void kernel_launch(void* const* d_in, const int* in_sizes, int n_in,
                              void* d_out, int out_size) {
    const float* u = (const float*)d_in[0];
    const float* A = (const float*)d_in[1];
    const float* B = (const float*)d_in[2];
    const float* C = (const float*)d_in[3];
    const float* D = (const float*)d_in[4];
    float* y = (float*)d_out;

    int sms = 0, dev = 0;
    cudaGetDevice(&dev);
    cudaDeviceGetAttribute(&sms, cudaDevAttrMultiProcessorCount, dev);
    if (sms <= 0) sms = 148;

    const int trinv_smem = (16384 + 16384 + 3 * 1024 + 128) * (int)sizeof(float);
    cudaFuncSetAttribute(trinv_kernel, cudaFuncAttributeMaxDynamicSharedMemorySize, trinv_smem);
    cudaFuncSetAttribute(gemm_kernel,  cudaFuncAttributeMaxDynamicSharedMemorySize, GSMEM_BYTES);

    trinv_kernel<<<1, 1024, trinv_smem>>>(A);
    xk_kernel<<<128, 128>>>(B);
    wk_kernel<<<128, 128>>>(C, D);
    gemm_kernel<<<sms, 256, GSMEM_BYTES>>>(u, y, sms);
}

// round 12
// speedup vs baseline: 1.4257x; 1.4257x over previous
#include <cuda_runtime.h>
#include <cuda_fp16.h>
#include <cstdint>

// ===========================================================================
// y = u @ W^T,  W = C (I-A)^{-1} B + D   (model is linear & time-invariant)
//
// Stage 1 solve_kernel : X = (I-A)^{-1} B, blocked forward substitution
//                        (round-8 variant: 1 block / 1024 thr, measured 17.6us)
// Stage 2 wk_kernel    : W = C X + D -> single fp16 swizzled ldmatrix image
// Stage 3 gemm_kernel  : persistent HMMA single-term fp16 GEMM y = uh*Wh.
//                        64-row tiles, 2 CTAs/SM (16 warps), double-buffered
//                        U, convert/STS interleaved into the MMA ks-loop.
//                        Error: u+W fp16 rounding ~2^-11 => rel_err ~4e-4.
// NOTE: tcgen05 unusable (harness PTX targets compute_103, no 'a').
// ===========================================================================

#define SDIM 128
#define N_ROWS (32 * 8192)
#define TILE64 64
#define N_TILES (N_ROWS / TILE64)     // 4096 tiles of 64 rows

__device__ float g_X[SDIM * SDIM];
__device__ __half g_Wh[SDIM * SDIM];   // swizzled ldmatrix image

__device__ __forceinline__ uint32_t smem_u32(const void* p) {
    return (uint32_t)__cvta_generic_to_shared(p);
}
__device__ __forceinline__ int swz_elem(int r, int k) {
    return r * 128 + ((((k >> 3) ^ (r & 7)) << 3) | (k & 7));
}

#define LDSM4(r, a) \
    asm volatile("ldmatrix.sync.aligned.m8n8.x4.shared.b16 {%0,%1,%2,%3}, [%4];" \
        : "=r"((r)[0]), "=r"((r)[1]), "=r"((r)[2]), "=r"((r)[3]) : "r"(a))

#define MMA16816H(d, a, b0, b1) \
    asm volatile("mma.sync.aligned.m16n8k16.row.col.f32.f16.f16.f32 " \
        "{%0,%1,%2,%3}, {%4,%5,%6,%7}, {%8,%9}, {%0,%1,%2,%3};" \
        : "+f"((d)[0]), "+f"((d)[1]), "+f"((d)[2]), "+f"((d)[3]) \
        : "r"((a)[0]), "r"((a)[1]), "r"((a)[2]), "r"((a)[3]), "r"(b0), "r"(b1))

// ===========================================================================
// Stage 1: blocked forward substitution, ONE block / 1024 threads (round 8).
// ===========================================================================
__global__ __launch_bounds__(1024, 1)
void solve_kernel(const float* __restrict__ A, const float* __restrict__ B) {
    extern __shared__ float sm1[];
    float* sA    = sm1;           // [128][128]
    float* sX    = sm1 + 16384;   // [128][128], init = B, becomes X
    float* rdiag = sX + 16384;    // [128]

    const int tid = threadIdx.x;

    for (int i = tid; i < 4096; i += 1024) {
        ((float4*)sA)[i] = ((const float4*)A)[i];
        ((float4*)sX)[i] = ((const float4*)B)[i];
    }
    __syncthreads();
    if (tid < 128) rdiag[tid] = 1.0f / (1.0f - sA[tid * 129]);
    __syncthreads();

    const int rp = tid >> 5;      // 0..7 (row group of 4) for update phase
    const int cg = tid & 31;      // float4 column group

    for (int I = 0; I < 4; I++) {
        const int r0 = I * 32;
        if (I > 0 && tid < 256) {
            float4 acc0 = {0,0,0,0}, acc1 = {0,0,0,0},
                   acc2 = {0,0,0,0}, acc3 = {0,0,0,0};
            const float* a0 = sA + (r0 + rp * 4 + 0) * 128;
            const float* a1 = sA + (r0 + rp * 4 + 1) * 128;
            const float* a2 = sA + (r0 + rp * 4 + 2) * 128;
            const float* a3 = sA + (r0 + rp * 4 + 3) * 128;
            #pragma unroll 4
            for (int j = 0; j < r0; j++) {
                float4 xv = *(float4*)(sX + j * 128 + 4 * cg);
                float b0 = a0[j], b1 = a1[j], b2 = a2[j], b3 = a3[j];
                acc0.x = fmaf(b0, xv.x, acc0.x); acc0.y = fmaf(b0, xv.y, acc0.y);
                acc0.z = fmaf(b0, xv.z, acc0.z); acc0.w = fmaf(b0, xv.w, acc0.w);
                acc1.x = fmaf(b1, xv.x, acc1.x); acc1.y = fmaf(b1, xv.y, acc1.y);
                acc1.z = fmaf(b1, xv.z, acc1.z); acc1.w = fmaf(b1, xv.w, acc1.w);
                acc2.x = fmaf(b2, xv.x, acc2.x); acc2.y = fmaf(b2, xv.y, acc2.y);
                acc2.z = fmaf(b2, xv.z, acc2.z); acc2.w = fmaf(b2, xv.w, acc2.w);
                acc3.x = fmaf(b3, xv.x, acc3.x); acc3.y = fmaf(b3, xv.y, acc3.y);
                acc3.z = fmaf(b3, xv.z, acc3.z); acc3.w = fmaf(b3, xv.w, acc3.w);
            }
            #pragma unroll
            for (int r = 0; r < 4; r++) {
                float4 av = (r == 0) ? acc0 : (r == 1) ? acc1 : (r == 2) ? acc2 : acc3;
                float4* dst = (float4*)(sX + (r0 + rp * 4 + r) * 128 + 4 * cg);
                float4 c = *dst;
                c.x += av.x; c.y += av.y; c.z += av.z; c.w += av.w;
                *dst = c;
            }
        }
        __syncthreads();
        if (tid < 128) {
            float xv[32], ac[32];
            #pragma unroll
            for (int q = 0; q < 32; q++) ac[q] = 0.f;
            #pragma unroll
            for (int j = 0; j < 32; j++) {
                float xj = (sX[(r0 + j) * 128 + tid] + ac[j]) * rdiag[r0 + j];
                xv[j] = xj;
                #pragma unroll
                for (int i2 = j + 1; i2 < 32; i2++)
                    ac[i2] = fmaf(sA[(r0 + i2) * 128 + r0 + j], xj, ac[i2]);
            }
            #pragma unroll
            for (int j = 0; j < 32; j++) sX[(r0 + j) * 128 + tid] = xv[j];
        }
        __syncthreads();
    }

    for (int i = tid; i < 4096; i += 1024)
        ((float4*)g_X)[i] = ((const float4*)sX)[i];
}

// ===========================================================================
// Stage 2: W[o][d] = sum_s C[o,s] X[s,d] + D[o,d] -> fp16 swizzled image
// ===========================================================================
__global__ void wk_kernel(const float* __restrict__ C, const float* __restrict__ Dm) {
    const int g = blockIdx.x * blockDim.x + threadIdx.x;
    const int o = g >> 7;
    const int d = g & (SDIM - 1);
    float acc = Dm[o * SDIM + d];
    #pragma unroll 8
    for (int s = 0; s < SDIM; s++)
        acc = fmaf(C[o * SDIM + s], g_X[s * SDIM + d], acc);
    g_Wh[swz_elem(o, d)] = __float2half_rn(acc);
}

// ===========================================================================
// Stage 3: persistent HMMA GEMM, single fp16 term, 64-row tiles, 2 CTAs/SM.
// SMEM/CTA: [0,32K) Wh | U buf p at 32K + p*16K  (total 64KB)
// Warp tile 32 rows x 32 cols: rg = w>>2 (2 x 32 rows), cq = w&3 (4 x 32 cols)
// ===========================================================================
#define GSMEM_BYTES (64 * 1024)
#define UBOFF(p) (32768u + (uint32_t)(p) * 16384u)

__global__ __launch_bounds__(256, 2)
void gemm_kernel(const float* __restrict__ u, float* __restrict__ y, int grid) {
    extern __shared__ __align__(16) unsigned char sm[];
    const uint32_t sbase = smem_u32(sm);

    const int tid  = threadIdx.x;
    const int lane = tid & 31;
    const int w    = tid >> 5;
    const int rg   = w >> 2;           // 0..1 : 32-row group
    const int cq   = w & 3;            // 0..3 : 32-col quarter
    const int Rw   = rg * 32;

    // W image -> SMEM
    {
        const uint4* sh = (const uint4*)g_Wh;
        uint4* dh = (uint4*)sm;
        for (int i = tid; i < 2048; i += 256) dh[i] = sh[i];
    }

    const int a_row  = Rw + (lane & 7) + ((lane >> 3) & 1) * 8;       // + rf*16
    const int a_kadd = ((lane >> 4) & 1) * 8;
    const int b_n    = cq * 32 + (lane & 7) + ((lane >> 4) & 1) * 8;  // + ng*16
    const int b_kadd = ((lane >> 3) & 1) * 8;
    const int r7     = lane & 7;

    // v: 8 float4 = one 64x128 tile / 256 threads
    float4 v[8];
    int tile = blockIdx.x;

    // ---- prologue: tile0 -> buf0; prefetch tile1 into regs ---------------
    if (tile < N_TILES) {
        const float4* src = (const float4*)u + (long)tile * 2048;
        #pragma unroll
        for (int j = 0; j < 8; j++) v[j] = src[tid + 256 * j];
        #pragma unroll
        for (int j = 0; j < 8; j++) {
            int uid = tid + 256 * j;
            int row = uid >> 5, kk = uid & 31;        // kk = 8B unit in row
            float4 p0 = v[j];
            __half2 h01 = __floats2half2_rn(p0.x, p0.y);
            __half2 h23 = __floats2half2_rn(p0.z, p0.w);
            int off = row * 256 + (((kk >> 1) ^ (row & 7)) << 4) + (kk & 1) * 8;
            *(uint2*)(sm + UBOFF(0) + off) =
                make_uint2(*(uint32_t*)&h01, *(uint32_t*)&h23);
        }
    }
    if (tile + grid < N_TILES) {
        const float4* src = (const float4*)u + (long)(tile + grid) * 2048;
        #pragma unroll
        for (int j = 0; j < 8; j++) v[j] = src[tid + 256 * j];
    }
    __syncthreads();

    int p = 0;
    for (; tile < N_TILES; tile += grid) {
        const bool hasNext = (tile + grid) < N_TILES;
        const uint32_t ub  = UBOFF(p);
        const uint32_t ubn = UBOFF(p ^ 1);

        float acc[2][4][4];
        #pragma unroll
        for (int rf = 0; rf < 2; rf++)
            #pragma unroll
            for (int nt = 0; nt < 4; nt++)
                #pragma unroll
                for (int q = 0; q < 4; q++) acc[rf][nt][q] = 0.f;

        #pragma unroll
        for (int ks = 0; ks < 8; ks++) {
            const int k0 = ks * 16;
            uint32_t ah[2][4];
            {
                int mk = k0 + a_kadd;
                uint32_t ad = sbase + ub +
                    (uint32_t)(a_row * 256 + (((mk >> 3) ^ r7) << 4));
                LDSM4(ah[0], ad);
                LDSM4(ah[1], ad + 4096u);     // +16 rows
            }
            #pragma unroll
            for (int ng = 0; ng < 2; ng++) {
                int n = b_n + ng * 16;
                int mk = k0 + b_kadd;
                uint32_t bd = sbase +
                    (uint32_t)(n * 256 + (((mk >> 3) ^ r7) << 4));
                uint32_t bh[4];
                LDSM4(bh, bd);
                const int nt = ng * 2;
                MMA16816H(acc[0][nt],     ah[0], bh[0], bh[1]);
                MMA16816H(acc[0][nt + 1], ah[0], bh[2], bh[3]);
                MMA16816H(acc[1][nt],     ah[1], bh[0], bh[1]);
                MMA16816H(acc[1][nt + 1], ah[1], bh[2], bh[3]);
            }
            // interleave next-tile convert/STS chunk (1 uint2 per thread)
            if (hasNext) {
                int uid = tid + 256 * ks;
                int row = uid >> 5, kk = uid & 31;
                float4 p0 = v[ks];
                __half2 h01 = __floats2half2_rn(p0.x, p0.y);
                __half2 h23 = __floats2half2_rn(p0.z, p0.w);
                int off = row * 256 + (((kk >> 1) ^ (row & 7)) << 4) + (kk & 1) * 8;
                *(uint2*)(sm + ubn + off) =
                    make_uint2(*(uint32_t*)&h01, *(uint32_t*)&h23);
            }
        }

        // epilogue: fragments -> y
        {
            const int q = lane >> 2, s2 = (lane & 3) * 2;
            #pragma unroll
            for (int rf = 0; rf < 2; rf++) {
                long grow = (long)tile * TILE64 + Rw + rf * 16 + q;
                float* yp0 = y + grow * SDIM + cq * 32 + s2;
                #pragma unroll
                for (int nt = 0; nt < 4; nt++) {
                    *(float2*)(yp0 + nt * 8) =
                        make_float2(acc[rf][nt][0], acc[rf][nt][1]);
                    *(float2*)(yp0 + 8 * SDIM + nt * 8) =
                        make_float2(acc[rf][nt][2], acc[rf][nt][3]);
                }
            }
        }

        // prefetch tile t+2 into regs
        if (tile + 2 * grid < N_TILES) {
            const float4* src = (const float4*)u + (long)(tile + 2 * grid) * 2048;
            #pragma unroll
            for (int j = 0; j < 8; j++) v[j] = src[tid + 256 * j];
        }
        __syncthreads();
        p ^= 1;
    }
}

// ===========================================================================
extern "C" void kernel_launch(void* const* d_in, const int* in_sizes, int n_in,
                              void* d_out, int out_size) {
    const float* u = (const float*)d_in[0];
    const float* A = (const float*)d_in[1];
    const float* B = (const float*)d_in[2];
    const float* C = (const float*)d_in[3];
    const float* D = (const float*)d_in[4];
    float* y = (float*)d_out;

    int sms = 0, dev = 0;
    cudaGetDevice(&dev);
    cudaDeviceGetAttribute(&sms, cudaDevAttrMultiProcessorCount, dev);
    if (sms <= 0) sms = 148;

    const int solve_smem = (16384 + 16384 + 128) * (int)sizeof(float);
    cudaFuncSetAttribute(solve_kernel, cudaFuncAttributeMaxDynamicSharedMemorySize, solve_smem);
    cudaFuncSetAttribute(gemm_kernel,  cudaFuncAttributeMaxDynamicSharedMemorySize, GSMEM_BYTES);

    solve_kernel<<<1, 1024, solve_smem>>>(A, B);
    wk_kernel<<<128, 128>>>(C, D);
    const int grid = 2 * sms;
    gemm_kernel<<<grid, 256, GSMEM_BYTES>>>(u, y, grid);
}